// round 6
// baseline (speedup 1.0000x reference)
#include <cuda_runtime.h>
#include <cuda_bf16.h>
#include <math.h>
#include <stdint.h>

// Problem constants
#define BB 2
#define SS 4096
#define DD 512
#define HH 8
#define DH 64
#define TT (BB * SS)   // 8192 tokens

// ---------------- scratch (device globals; no allocations allowed) ----------
__device__ float g_Q[TT * DD];
__device__ float g_K[TT * DD];
__device__ float g_V[TT * DD];
__device__ float g_A[TT * DD];

// ---------------------------------------------------------------------------
// tf32 helpers (mma.sync m16n8k8 — sm_100 baseline ISA)
// ---------------------------------------------------------------------------
__device__ __forceinline__ unsigned f2tf(float f) {
    unsigned u;
    asm("cvt.rna.tf32.f32 %0, %1;" : "=r"(u) : "f"(f));
    return u;
}
__device__ __forceinline__ float f2tf_f(float f) {
    return __uint_as_float(f2tf(f));
}
__device__ __forceinline__ void mma_tf32(float c[4],
                                         unsigned a0, unsigned a1,
                                         unsigned a2, unsigned a3,
                                         unsigned b0, unsigned b1) {
    asm volatile(
        "mma.sync.aligned.m16n8k8.row.col.f32.tf32.tf32.f32 "
        "{%0,%1,%2,%3}, {%4,%5,%6,%7}, {%8,%9}, {%0,%1,%2,%3};"
        : "+f"(c[0]), "+f"(c[1]), "+f"(c[2]), "+f"(c[3])
        : "r"(a0), "r"(a1), "r"(a2), "r"(a3), "r"(b0), "r"(b1));
}

// ============================================================================
// GEMM (unchanged): out = X @ W^T + bias, tf32 mma.sync
// ============================================================================
__global__ __launch_bounds__(256, 2)
void gemm_mma(const float* __restrict__ X, const float* __restrict__ W,
              const float* __restrict__ bias, float* __restrict__ out,
              int M, int N, int K) {
    __shared__ float Xs[128][20];
    __shared__ float Ws[128][20];

    const int tid  = threadIdx.x;
    const int lane = tid & 31;
    const int warp = tid >> 5;
    const int g = lane >> 2;
    const int t = lane & 3;
    const int wm = (warp >> 2) * 64;
    const int wn = (warp & 3) * 32;
    const int m0 = blockIdx.x * 128;
    const int n0 = blockIdx.y * 128;

    const int lr = tid >> 1;
    const int lc = (tid & 1) * 8;

    float c[4][4][4];
#pragma unroll
    for (int i = 0; i < 4; i++)
#pragma unroll
        for (int j = 0; j < 4; j++)
#pragma unroll
            for (int r = 0; r < 4; r++) c[i][j][r] = 0.f;

    for (int kt = 0; kt < K; kt += 16) {
        __syncthreads();
        {
            const float* xp = &X[(size_t)(m0 + lr) * K + kt + lc];
            float4 v0 = *(const float4*)xp;
            float4 v1 = *(const float4*)(xp + 4);
            Xs[lr][lc + 0] = f2tf_f(v0.x); Xs[lr][lc + 1] = f2tf_f(v0.y);
            Xs[lr][lc + 2] = f2tf_f(v0.z); Xs[lr][lc + 3] = f2tf_f(v0.w);
            Xs[lr][lc + 4] = f2tf_f(v1.x); Xs[lr][lc + 5] = f2tf_f(v1.y);
            Xs[lr][lc + 6] = f2tf_f(v1.z); Xs[lr][lc + 7] = f2tf_f(v1.w);
            const float* wp = &W[(size_t)(n0 + lr) * K + kt + lc];
            float4 w0 = *(const float4*)wp;
            float4 w1 = *(const float4*)(wp + 4);
            Ws[lr][lc + 0] = f2tf_f(w0.x); Ws[lr][lc + 1] = f2tf_f(w0.y);
            Ws[lr][lc + 2] = f2tf_f(w0.z); Ws[lr][lc + 3] = f2tf_f(w0.w);
            Ws[lr][lc + 4] = f2tf_f(w1.x); Ws[lr][lc + 5] = f2tf_f(w1.y);
            Ws[lr][lc + 6] = f2tf_f(w1.z); Ws[lr][lc + 7] = f2tf_f(w1.w);
        }
        __syncthreads();

#pragma unroll
        for (int k8 = 0; k8 < 16; k8 += 8) {
            unsigned a[4][4], b[4][2];
#pragma unroll
            for (int mi = 0; mi < 4; mi++) {
                int rb = wm + mi * 16;
                a[mi][0] = __float_as_uint(Xs[rb + g][k8 + t]);
                a[mi][1] = __float_as_uint(Xs[rb + g + 8][k8 + t]);
                a[mi][2] = __float_as_uint(Xs[rb + g][k8 + t + 4]);
                a[mi][3] = __float_as_uint(Xs[rb + g + 8][k8 + t + 4]);
            }
#pragma unroll
            for (int nj = 0; nj < 4; nj++) {
                int nb = wn + nj * 8;
                b[nj][0] = __float_as_uint(Ws[nb + g][k8 + t]);
                b[nj][1] = __float_as_uint(Ws[nb + g][k8 + t + 4]);
            }
#pragma unroll
            for (int mi = 0; mi < 4; mi++)
#pragma unroll
                for (int nj = 0; nj < 4; nj++)
                    mma_tf32(c[mi][nj], a[mi][0], a[mi][1], a[mi][2], a[mi][3],
                             b[nj][0], b[nj][1]);
        }
    }

#pragma unroll
    for (int mi = 0; mi < 4; mi++) {
#pragma unroll
        for (int nj = 0; nj < 4; nj++) {
            int row = m0 + wm + mi * 16 + g;
            int col = n0 + wn + nj * 8 + 2 * t;
            float2 bv = *(const float2*)&bias[col];
            float2 r0, r1;
            r0.x = c[mi][nj][0] + bv.x;
            r0.y = c[mi][nj][1] + bv.y;
            r1.x = c[mi][nj][2] + bv.x;
            r1.y = c[mi][nj][3] + bv.y;
            *(float2*)&out[(size_t)row * N + col] = r0;
            *(float2*)&out[(size_t)(row + 8) * N + col] = r1;
        }
    }
}

// ============================================================================
// Flash attention, tf32 mma.sync, warp_M = 32, NO P staging (shuffle xform).
// Grid (S/128, H, B), 128 threads = 4 warps, 2 CTAs/SM.
// Q fragments in registers; K/V in SMEM (36KB); P accum->A-frag via shuffles.
// ============================================================================
#define KST 72
#define PST 68      // Q staging stride (overlaid on K/V area before main loop)
#define QTILE 128

__global__ __launch_bounds__(128, 2)
void attn_mma(const float* __restrict__ Qg, const float* __restrict__ Kg,
              const float* __restrict__ Vg, float* __restrict__ Og) {
    __shared__ float sm[2 * 64 * KST];   // Ks | Vs ; Q staged here pre-loop
    float* Ks = sm;
    float* Vs = sm + 64 * KST;

    const int b  = blockIdx.z;
    const int h  = blockIdx.y;
    const int q0 = blockIdx.x * QTILE;
    const int tid  = threadIdx.x;
    const int lane = tid & 31;
    const int warp = tid >> 5;
    const int g = lane >> 2;
    const int t = lane & 3;
    const int wq = warp * 32;          // warp's query-row offset (4 warps x 32)
    const float scale = 0.125f;        // 1/sqrt(64)
    const unsigned FULL = 0xffffffffu;

    // ---- stage Q tile into smem (overlaid), tf32-rounded & pre-scaled ----
    {
        int r = tid;                   // one row per thread (128 rows)
        const float* src = Qg + (size_t)(b * SS + q0 + r) * DD + h * DH;
#pragma unroll
        for (int dd = 0; dd < 64; dd += 4) {
            float4 v = *(const float4*)(src + dd);
            sm[r * PST + dd + 0] = f2tf_f(v.x * scale);
            sm[r * PST + dd + 1] = f2tf_f(v.y * scale);
            sm[r * PST + dd + 2] = f2tf_f(v.z * scale);
            sm[r * PST + dd + 3] = f2tf_f(v.w * scale);
        }
    }
    __syncthreads();

    // ---- Q fragments to registers: aq[k8][mi][4] ----
    unsigned aq[8][2][4];
#pragma unroll
    for (int k8 = 0; k8 < 8; k8++) {
#pragma unroll
        for (int mi = 0; mi < 2; mi++) {
            int rb = wq + mi * 16;
            aq[k8][mi][0] = __float_as_uint(sm[(rb + g) * PST + k8 * 8 + t]);
            aq[k8][mi][1] = __float_as_uint(sm[(rb + g + 8) * PST + k8 * 8 + t]);
            aq[k8][mi][2] = __float_as_uint(sm[(rb + g) * PST + k8 * 8 + t + 4]);
            aq[k8][mi][3] = __float_as_uint(sm[(rb + g + 8) * PST + k8 * 8 + t + 4]);
        }
    }
    __syncthreads();   // staging area about to be overwritten by K/V

    float o[2][8][4];
#pragma unroll
    for (int mi = 0; mi < 2; mi++)
#pragma unroll
        for (int n = 0; n < 8; n++)
#pragma unroll
            for (int r = 0; r < 4; r++) o[mi][n][r] = 0.f;
    float mrow[2][2] = {{-1e30f, -1e30f}, {-1e30f, -1e30f}};
    float lrow[2][2] = {{0.f, 0.f}, {0.f, 0.f}};

    const int jl  = tid >> 1;          // 0..63 key row for loads
    const int dl0 = (tid & 1) * 32;    // d offset for loads (two 32-halves)
    const float* kb = Kg + (size_t)(b * SS) * DD + h * DH;
    const float* vb = Vg + (size_t)(b * SS) * DD + h * DH;

    for (int kt = 0; kt < SS; kt += 64) {
        __syncthreads();   // prev-iter K/V consumers done (and Q frags read)
        // ---- load K/V chunk (tf32-rounded), 32 floats each per thread ----
#pragma unroll
        for (int dd = 0; dd < 32; dd += 4) {
            float4 kv = *(const float4*)(kb + (size_t)(kt + jl) * DD + dl0 + dd);
            Ks[jl * KST + dl0 + dd + 0] = f2tf_f(kv.x);
            Ks[jl * KST + dl0 + dd + 1] = f2tf_f(kv.y);
            Ks[jl * KST + dl0 + dd + 2] = f2tf_f(kv.z);
            Ks[jl * KST + dl0 + dd + 3] = f2tf_f(kv.w);
            float4 vv = *(const float4*)(vb + (size_t)(kt + jl) * DD + dl0 + dd);
            Vs[jl * KST + dl0 + dd + 0] = f2tf_f(vv.x);
            Vs[jl * KST + dl0 + dd + 1] = f2tf_f(vv.y);
            Vs[jl * KST + dl0 + dd + 2] = f2tf_f(vv.z);
            Vs[jl * KST + dl0 + dd + 3] = f2tf_f(vv.w);
        }
        __syncthreads();

        // ---- S = Q @ K^T (warp tile 32 x 64) ----
        float s[2][8][4];
#pragma unroll
        for (int mi = 0; mi < 2; mi++)
#pragma unroll
            for (int n = 0; n < 8; n++)
#pragma unroll
                for (int r = 0; r < 4; r++) s[mi][n][r] = 0.f;
#pragma unroll
        for (int k8 = 0; k8 < 8; k8++) {
#pragma unroll
            for (int n = 0; n < 8; n++) {
                unsigned b0 = __float_as_uint(Ks[(n * 8 + g) * KST + k8 * 8 + t]);
                unsigned b1 = __float_as_uint(Ks[(n * 8 + g) * KST + k8 * 8 + t + 4]);
#pragma unroll
                for (int mi = 0; mi < 2; mi++)
                    mma_tf32(s[mi][n], aq[k8][mi][0], aq[k8][mi][1],
                             aq[k8][mi][2], aq[k8][mi][3], b0, b1);
            }
        }

        // ---- online softmax on fragment rows (P kept in registers) ----
#pragma unroll
        for (int mi = 0; mi < 2; mi++) {
#pragma unroll
            for (int half = 0; half < 2; half++) {
                const int i0 = half * 2;
                float mx = -1e30f;
#pragma unroll
                for (int n = 0; n < 8; n++)
                    mx = fmaxf(mx, fmaxf(s[mi][n][i0], s[mi][n][i0 + 1]));
                mx = fmaxf(mx, __shfl_xor_sync(FULL, mx, 1));
                mx = fmaxf(mx, __shfl_xor_sync(FULL, mx, 2));
                float mnew  = fmaxf(mrow[mi][half], mx);
                float alpha = __expf(mrow[mi][half] - mnew);
                float psum  = 0.f;
#pragma unroll
                for (int n = 0; n < 8; n++) {
                    float p0 = __expf(s[mi][n][i0] - mnew);
                    float p1 = __expf(s[mi][n][i0 + 1] - mnew);
                    psum += p0 + p1;
                    s[mi][n][i0]     = f2tf_f(p0);
                    s[mi][n][i0 + 1] = f2tf_f(p1);
                }
                psum += __shfl_xor_sync(FULL, psum, 1);
                psum += __shfl_xor_sync(FULL, psum, 2);
                lrow[mi][half] = lrow[mi][half] * alpha + psum;
                mrow[mi][half] = mnew;
#pragma unroll
                for (int n = 0; n < 8; n++) {
                    o[mi][n][i0]     *= alpha;
                    o[mi][n][i0 + 1] *= alpha;
                }
            }
        }

        // ---- O += P @ V : P accum-layout -> A-frag via shuffles ----
        // owner of P[r][c] (16x8 tile): lane (r&7)*4 + (c>>1), reg 2*(r>=8)+(c&1)
        const int src0 = (lane & ~3) | (t >> 1);   // for cols t
        const int src1 = src0 | 2;                 // for cols t+4
        const bool odd = (t & 1) != 0;
#pragma unroll
        for (int k8 = 0; k8 < 8; k8++) {
            unsigned pa[2][4];
#pragma unroll
            for (int mi = 0; mi < 2; mi++) {
                float q00 = __shfl_sync(FULL, s[mi][k8][0], src0);
                float q01 = __shfl_sync(FULL, s[mi][k8][1], src0);
                float q10 = __shfl_sync(FULL, s[mi][k8][2], src0);
                float q11 = __shfl_sync(FULL, s[mi][k8][3], src0);
                float q20 = __shfl_sync(FULL, s[mi][k8][0], src1);
                float q21 = __shfl_sync(FULL, s[mi][k8][1], src1);
                float q30 = __shfl_sync(FULL, s[mi][k8][2], src1);
                float q31 = __shfl_sync(FULL, s[mi][k8][3], src1);
                pa[mi][0] = __float_as_uint(odd ? q01 : q00);  // P[g][t]
                pa[mi][1] = __float_as_uint(odd ? q11 : q10);  // P[g+8][t]
                pa[mi][2] = __float_as_uint(odd ? q21 : q20);  // P[g][t+4]
                pa[mi][3] = __float_as_uint(odd ? q31 : q30);  // P[g+8][t+4]
            }
#pragma unroll
            for (int n = 0; n < 8; n++) {
                unsigned b0 = __float_as_uint(Vs[(k8 * 8 + t) * KST + n * 8 + g]);
                unsigned b1 = __float_as_uint(Vs[(k8 * 8 + t + 4) * KST + n * 8 + g]);
#pragma unroll
                for (int mi = 0; mi < 2; mi++)
                    mma_tf32(o[mi][n], pa[mi][0], pa[mi][1], pa[mi][2], pa[mi][3],
                             b0, b1);
            }
        }
    }

    // ---- epilogue: normalize, write merged-head layout ----
#pragma unroll
    for (int mi = 0; mi < 2; mi++) {
        float inv0 = 1.f / lrow[mi][0];
        float inv1 = 1.f / lrow[mi][1];
#pragma unroll
        for (int n = 0; n < 8; n++) {
            int row = q0 + wq + mi * 16 + g;
            int col = h * DH + n * 8 + 2 * t;
            float* dst0 = Og + (size_t)(b * SS + row) * DD + col;
            float* dst1 = Og + (size_t)(b * SS + row + 8) * DD + col;
            *(float2*)dst0 = make_float2(o[mi][n][0] * inv0, o[mi][n][1] * inv0);
            *(float2*)dst1 = make_float2(o[mi][n][2] * inv1, o[mi][n][3] * inv1);
        }
    }
}

// ============================================================================
// kernel_launch
// ============================================================================
extern "C" void kernel_launch(void* const* d_in, const int* in_sizes, int n_in,
                              void* d_out, int out_size) {
    const float* q  = (const float*)d_in[0];
    const float* Wq = (const float*)d_in[1];
    const float* bq = (const float*)d_in[2];
    const float* Wk = (const float*)d_in[3];
    const float* bk = (const float*)d_in[4];
    const float* Wv = (const float*)d_in[5];
    const float* bv = (const float*)d_in[6];
    const float* Wo = (const float*)d_in[7];
    const float* bo = (const float*)d_in[8];
    float* out = (float*)d_out;

    float *gq, *gk, *gv, *ga;
    cudaGetSymbolAddress((void**)&gq, g_Q);
    cudaGetSymbolAddress((void**)&gk, g_K);
    cudaGetSymbolAddress((void**)&gv, g_V);
    cudaGetSymbolAddress((void**)&ga, g_A);

    dim3 gemm_grid(TT / 128, DD / 128);  // (64, 4)
    dim3 gemm_block(256);

    gemm_mma<<<gemm_grid, gemm_block>>>(q, Wq, bq, gq, TT, DD, DD);
    gemm_mma<<<gemm_grid, gemm_block>>>(q, Wk, bk, gk, TT, DD, DD);
    gemm_mma<<<gemm_grid, gemm_block>>>(q, Wv, bv, gv, TT, DD, DD);

    dim3 attn_grid(SS / QTILE, HH, BB);  // (32, 8, 2)
    attn_mma<<<attn_grid, 128>>>(gq, gk, gv, ga);

    gemm_mma<<<gemm_grid, gemm_block>>>(ga, Wo, bo, out, TT, DD, DD);
}

// round 7
// speedup vs baseline: 1.1899x; 1.1899x over previous
#include <cuda_runtime.h>
#include <cuda_bf16.h>
#include <math.h>
#include <stdint.h>

// Problem constants
#define BB 2
#define SS 4096
#define DD 512
#define HH 8
#define DH 64
#define TT (BB * SS)   // 8192 tokens

// ---------------- scratch (device globals; no allocations allowed) ----------
__device__ float g_Q[TT * DD];
__device__ float g_K[TT * DD];
__device__ float g_V[TT * DD];
__device__ float g_A[TT * DD];

// ---------------------------------------------------------------------------
// tf32 helpers (mma.sync m16n8k8 — sm_100 baseline ISA)
// ---------------------------------------------------------------------------
__device__ __forceinline__ unsigned f2tf(float f) {
    unsigned u;
    asm("cvt.rna.tf32.f32 %0, %1;" : "=r"(u) : "f"(f));
    return u;
}
__device__ __forceinline__ float f2tf_f(float f) {
    return __uint_as_float(f2tf(f));
}
__device__ __forceinline__ void mma_tf32(float c[4],
                                         unsigned a0, unsigned a1,
                                         unsigned a2, unsigned a3,
                                         unsigned b0, unsigned b1) {
    asm volatile(
        "mma.sync.aligned.m16n8k8.row.col.f32.tf32.tf32.f32 "
        "{%0,%1,%2,%3}, {%4,%5,%6,%7}, {%8,%9}, {%0,%1,%2,%3};"
        : "+f"(c[0]), "+f"(c[1]), "+f"(c[2]), "+f"(c[3])
        : "r"(a0), "r"(a1), "r"(a2), "r"(a3), "r"(b0), "r"(b1));
}

// ============================================================================
// GEMM: out = X @ W^T + bias, tf32 mma.sync, double-buffered SMEM.
// Block 128x128, BK=16, 256 threads = 8 warps (2x4), warp tile 64x32.
// ============================================================================
__global__ __launch_bounds__(256, 2)
void gemm_mma(const float* __restrict__ X, const float* __restrict__ W,
              const float* __restrict__ bias, float* __restrict__ out,
              int M, int N, int K) {
    __shared__ float Xs[2][128][20];
    __shared__ float Ws[2][128][20];

    const int tid  = threadIdx.x;
    const int lane = tid & 31;
    const int warp = tid >> 5;
    const int g = lane >> 2;
    const int t = lane & 3;
    const int wm = (warp >> 2) * 64;
    const int wn = (warp & 3) * 32;
    const int m0 = blockIdx.x * 128;
    const int n0 = blockIdx.y * 128;

    const int lr = tid >> 1;
    const int lc = (tid & 1) * 8;

    const float* xp0 = &X[(size_t)(m0 + lr) * K + lc];
    const float* wp0 = &W[(size_t)(n0 + lr) * K + lc];

    float xr[8], wr[8];
    // prologue: load kt=0 into regs, store (rounded) into buf 0
    {
        float4 v0 = *(const float4*)xp0;
        float4 v1 = *(const float4*)(xp0 + 4);
        xr[0]=v0.x; xr[1]=v0.y; xr[2]=v0.z; xr[3]=v0.w;
        xr[4]=v1.x; xr[5]=v1.y; xr[6]=v1.z; xr[7]=v1.w;
        float4 w0 = *(const float4*)wp0;
        float4 w1 = *(const float4*)(wp0 + 4);
        wr[0]=w0.x; wr[1]=w0.y; wr[2]=w0.z; wr[3]=w0.w;
        wr[4]=w1.x; wr[5]=w1.y; wr[6]=w1.z; wr[7]=w1.w;
#pragma unroll
        for (int i = 0; i < 8; i++) {
            Xs[0][lr][lc + i] = f2tf_f(xr[i]);
            Ws[0][lr][lc + i] = f2tf_f(wr[i]);
        }
    }
    __syncthreads();

    float c[4][4][4];
#pragma unroll
    for (int i = 0; i < 4; i++)
#pragma unroll
        for (int j = 0; j < 4; j++)
#pragma unroll
            for (int r = 0; r < 4; r++) c[i][j][r] = 0.f;

    int cur = 0;
    for (int kt = 0; kt < K; kt += 16) {
        const bool has_next = (kt + 16) < K;
        if (has_next) {
            const float* xp = xp0 + kt + 16;
            float4 v0 = *(const float4*)xp;
            float4 v1 = *(const float4*)(xp + 4);
            xr[0]=v0.x; xr[1]=v0.y; xr[2]=v0.z; xr[3]=v0.w;
            xr[4]=v1.x; xr[5]=v1.y; xr[6]=v1.z; xr[7]=v1.w;
            const float* wp = wp0 + kt + 16;
            float4 w0 = *(const float4*)wp;
            float4 w1 = *(const float4*)(wp + 4);
            wr[0]=w0.x; wr[1]=w0.y; wr[2]=w0.z; wr[3]=w0.w;
            wr[4]=w1.x; wr[5]=w1.y; wr[6]=w1.z; wr[7]=w1.w;
        }

#pragma unroll
        for (int k8 = 0; k8 < 16; k8 += 8) {
            unsigned a[4][4], b[4][2];
#pragma unroll
            for (int mi = 0; mi < 4; mi++) {
                int rb = wm + mi * 16;
                a[mi][0] = __float_as_uint(Xs[cur][rb + g][k8 + t]);
                a[mi][1] = __float_as_uint(Xs[cur][rb + g + 8][k8 + t]);
                a[mi][2] = __float_as_uint(Xs[cur][rb + g][k8 + t + 4]);
                a[mi][3] = __float_as_uint(Xs[cur][rb + g + 8][k8 + t + 4]);
            }
#pragma unroll
            for (int nj = 0; nj < 4; nj++) {
                int nb = wn + nj * 8;
                b[nj][0] = __float_as_uint(Ws[cur][nb + g][k8 + t]);
                b[nj][1] = __float_as_uint(Ws[cur][nb + g][k8 + t + 4]);
            }
#pragma unroll
            for (int mi = 0; mi < 4; mi++)
#pragma unroll
                for (int nj = 0; nj < 4; nj++)
                    mma_tf32(c[mi][nj], a[mi][0], a[mi][1], a[mi][2], a[mi][3],
                             b[nj][0], b[nj][1]);
        }

        if (has_next) {
            int nxt = cur ^ 1;
#pragma unroll
            for (int i = 0; i < 8; i++) {
                Xs[nxt][lr][lc + i] = f2tf_f(xr[i]);
                Ws[nxt][lr][lc + i] = f2tf_f(wr[i]);
            }
            __syncthreads();
            cur = nxt;
        }
    }

#pragma unroll
    for (int mi = 0; mi < 4; mi++) {
#pragma unroll
        for (int nj = 0; nj < 4; nj++) {
            int row = m0 + wm + mi * 16 + g;
            int col = n0 + wn + nj * 8 + 2 * t;
            float2 bv = *(const float2*)&bias[col];
            float2 r0, r1;
            r0.x = c[mi][nj][0] + bv.x;
            r0.y = c[mi][nj][1] + bv.y;
            r1.x = c[mi][nj][2] + bv.x;
            r1.y = c[mi][nj][3] + bv.y;
            *(float2*)&out[(size_t)row * N + col] = r0;
            *(float2*)&out[(size_t)(row + 8) * N + col] = r1;
        }
    }
}

// ============================================================================
// Flash attention, tf32 mma.sync, warp_M = 32, P staged via SMEM (R5 base).
// Grid (S/256, H, B), 256 threads = 8 warps; warp owns 32 query rows.
// Bank-conflict fix: Ks stride 68 (bank = 4g+t, conflict-free),
//                    Vs stride 72 (bank = 8t+g, conflict-free).
// SMEM: Ks[64][68], Vs[64][72], Ps[256][68].
// ============================================================================
#define KSTK 68
#define KSTV 72
#define PST 68
#define QTILE 256
#define ATTN_SMEM_BYTES ((64 * KSTK + 64 * KSTV + QTILE * PST) * 4)

__global__ __launch_bounds__(256, 1)
void attn_mma(const float* __restrict__ Qg, const float* __restrict__ Kg,
              const float* __restrict__ Vg, float* __restrict__ Og) {
    extern __shared__ float sm[];
    float* Ks = sm;                     // [64][68]
    float* Vs = Ks + 64 * KSTK;         // [64][72]
    float* Ps = Vs + 64 * KSTV;         // [256][68]

    const int b  = blockIdx.z;
    const int h  = blockIdx.y;
    const int q0 = blockIdx.x * QTILE;
    const int tid  = threadIdx.x;
    const int lane = tid & 31;
    const int warp = tid >> 5;
    const int g = lane >> 2;
    const int t = lane & 3;
    const int wq = warp * 32;          // warp's query-row offset in tile
    const float scale = 0.125f;        // 1/sqrt(64)
    const unsigned FULL = 0xffffffffu;

    // ---- stage Q tile into Ps (tf32-rounded, pre-scaled) ----
    {
        int r = tid;                   // one row per thread
        const float* src = Qg + (size_t)(b * SS + q0 + r) * DD + h * DH;
#pragma unroll
        for (int dd = 0; dd < 64; dd += 4) {
            float4 v = *(const float4*)(src + dd);
            Ps[r * PST + dd + 0] = f2tf_f(v.x * scale);
            Ps[r * PST + dd + 1] = f2tf_f(v.y * scale);
            Ps[r * PST + dd + 2] = f2tf_f(v.z * scale);
            Ps[r * PST + dd + 3] = f2tf_f(v.w * scale);
        }
    }
    __syncthreads();

    // ---- Q fragments to registers: aq[k8][mi][4]  (mi = m-tile 0/1) ----
    unsigned aq[8][2][4];
#pragma unroll
    for (int k8 = 0; k8 < 8; k8++) {
#pragma unroll
        for (int mi = 0; mi < 2; mi++) {
            int rb = wq + mi * 16;
            aq[k8][mi][0] = __float_as_uint(Ps[(rb + g) * PST + k8 * 8 + t]);
            aq[k8][mi][1] = __float_as_uint(Ps[(rb + g + 8) * PST + k8 * 8 + t]);
            aq[k8][mi][2] = __float_as_uint(Ps[(rb + g) * PST + k8 * 8 + t + 4]);
            aq[k8][mi][3] = __float_as_uint(Ps[(rb + g + 8) * PST + k8 * 8 + t + 4]);
        }
    }

    float o[2][8][4];
#pragma unroll
    for (int mi = 0; mi < 2; mi++)
#pragma unroll
        for (int n = 0; n < 8; n++)
#pragma unroll
            for (int r = 0; r < 4; r++) o[mi][n][r] = 0.f;
    float mrow[2][2] = {{-1e30f, -1e30f}, {-1e30f, -1e30f}};
    float lrow[2][2] = {{0.f, 0.f}, {0.f, 0.f}};

    const int jl  = tid >> 2;          // 0..63 key row for loads
    const int dl0 = (tid & 3) * 16;    // d offset for loads
    const float* kb = Kg + (size_t)(b * SS) * DD + h * DH;
    const float* vb = Vg + (size_t)(b * SS) * DD + h * DH;

    for (int kt = 0; kt < SS; kt += 64) {
        __syncthreads();   // prev-iter K/V/P consumers done
        // ---- load K/V chunk (tf32-rounded) ----
#pragma unroll
        for (int dd = 0; dd < 16; dd += 4) {
            float4 kv = *(const float4*)(kb + (size_t)(kt + jl) * DD + dl0 + dd);
            Ks[jl * KSTK + dl0 + dd + 0] = f2tf_f(kv.x);
            Ks[jl * KSTK + dl0 + dd + 1] = f2tf_f(kv.y);
            Ks[jl * KSTK + dl0 + dd + 2] = f2tf_f(kv.z);
            Ks[jl * KSTK + dl0 + dd + 3] = f2tf_f(kv.w);
            float4 vv = *(const float4*)(vb + (size_t)(kt + jl) * DD + dl0 + dd);
            Vs[jl * KSTV + dl0 + dd + 0] = f2tf_f(vv.x);
            Vs[jl * KSTV + dl0 + dd + 1] = f2tf_f(vv.y);
            Vs[jl * KSTV + dl0 + dd + 2] = f2tf_f(vv.z);
            Vs[jl * KSTV + dl0 + dd + 3] = f2tf_f(vv.w);
        }
        __syncthreads();

        // ---- S = Q @ K^T (warp tile 32 x 64) ----
        float s[2][8][4];
#pragma unroll
        for (int mi = 0; mi < 2; mi++)
#pragma unroll
            for (int n = 0; n < 8; n++)
#pragma unroll
                for (int r = 0; r < 4; r++) s[mi][n][r] = 0.f;
#pragma unroll
        for (int k8 = 0; k8 < 8; k8++) {
#pragma unroll
            for (int n = 0; n < 8; n++) {
                unsigned b0 = __float_as_uint(Ks[(n * 8 + g) * KSTK + k8 * 8 + t]);
                unsigned b1 = __float_as_uint(Ks[(n * 8 + g) * KSTK + k8 * 8 + t + 4]);
#pragma unroll
                for (int mi = 0; mi < 2; mi++)
                    mma_tf32(s[mi][n], aq[k8][mi][0], aq[k8][mi][1],
                             aq[k8][mi][2], aq[k8][mi][3], b0, b1);
            }
        }

        // ---- online softmax on fragment rows, stage P to SMEM ----
#pragma unroll
        for (int mi = 0; mi < 2; mi++) {
#pragma unroll
            for (int half = 0; half < 2; half++) {
                const int i0 = half * 2;
                float mx = -1e30f;
#pragma unroll
                for (int n = 0; n < 8; n++)
                    mx = fmaxf(mx, fmaxf(s[mi][n][i0], s[mi][n][i0 + 1]));
                mx = fmaxf(mx, __shfl_xor_sync(FULL, mx, 1));
                mx = fmaxf(mx, __shfl_xor_sync(FULL, mx, 2));
                float mnew  = fmaxf(mrow[mi][half], mx);
                float alpha = __expf(mrow[mi][half] - mnew);
                float psum  = 0.f;
                int r = wq + mi * 16 + g + half * 8;
#pragma unroll
                for (int n = 0; n < 8; n++) {
                    float p0 = __expf(s[mi][n][i0] - mnew);
                    float p1 = __expf(s[mi][n][i0 + 1] - mnew);
                    psum += p0 + p1;
                    *(float2*)&Ps[r * PST + n * 8 + 2 * t] =
                        make_float2(f2tf_f(p0), f2tf_f(p1));
                }
                psum += __shfl_xor_sync(FULL, psum, 1);
                psum += __shfl_xor_sync(FULL, psum, 2);
                lrow[mi][half] = lrow[mi][half] * alpha + psum;
                mrow[mi][half] = mnew;
#pragma unroll
                for (int n = 0; n < 8; n++) {
                    o[mi][n][i0]     *= alpha;
                    o[mi][n][i0 + 1] *= alpha;
                }
            }
        }
        __syncwarp();   // P rows are warp-private; order STS before LDS

        // ---- O += P @ V ----
#pragma unroll
        for (int k8 = 0; k8 < 8; k8++) {
            unsigned pa[2][4];
#pragma unroll
            for (int mi = 0; mi < 2; mi++) {
                int rb = wq + mi * 16;
                pa[mi][0] = __float_as_uint(Ps[(rb + g) * PST + k8 * 8 + t]);
                pa[mi][1] = __float_as_uint(Ps[(rb + g + 8) * PST + k8 * 8 + t]);
                pa[mi][2] = __float_as_uint(Ps[(rb + g) * PST + k8 * 8 + t + 4]);
                pa[mi][3] = __float_as_uint(Ps[(rb + g + 8) * PST + k8 * 8 + t + 4]);
            }
#pragma unroll
            for (int n = 0; n < 8; n++) {
                unsigned b0 = __float_as_uint(Vs[(k8 * 8 + t) * KSTV + n * 8 + g]);
                unsigned b1 = __float_as_uint(Vs[(k8 * 8 + t + 4) * KSTV + n * 8 + g]);
#pragma unroll
                for (int mi = 0; mi < 2; mi++)
                    mma_tf32(o[mi][n], pa[mi][0], pa[mi][1], pa[mi][2], pa[mi][3],
                             b0, b1);
            }
        }
    }

    // ---- epilogue: normalize, write merged-head layout ----
#pragma unroll
    for (int mi = 0; mi < 2; mi++) {
        float inv0 = 1.f / lrow[mi][0];
        float inv1 = 1.f / lrow[mi][1];
#pragma unroll
        for (int n = 0; n < 8; n++) {
            int row = q0 + wq + mi * 16 + g;
            int col = h * DH + n * 8 + 2 * t;
            float* dst0 = Og + (size_t)(b * SS + row) * DD + col;
            float* dst1 = Og + (size_t)(b * SS + row + 8) * DD + col;
            *(float2*)dst0 = make_float2(o[mi][n][0] * inv0, o[mi][n][1] * inv0);
            *(float2*)dst1 = make_float2(o[mi][n][2] * inv1, o[mi][n][3] * inv1);
        }
    }
}

// ============================================================================
// kernel_launch
// ============================================================================
extern "C" void kernel_launch(void* const* d_in, const int* in_sizes, int n_in,
                              void* d_out, int out_size) {
    const float* q  = (const float*)d_in[0];
    const float* Wq = (const float*)d_in[1];
    const float* bq = (const float*)d_in[2];
    const float* Wk = (const float*)d_in[3];
    const float* bk = (const float*)d_in[4];
    const float* Wv = (const float*)d_in[5];
    const float* bv = (const float*)d_in[6];
    const float* Wo = (const float*)d_in[7];
    const float* bo = (const float*)d_in[8];
    float* out = (float*)d_out;

    float *gq, *gk, *gv, *ga;
    cudaGetSymbolAddress((void**)&gq, g_Q);
    cudaGetSymbolAddress((void**)&gk, g_K);
    cudaGetSymbolAddress((void**)&gv, g_V);
    cudaGetSymbolAddress((void**)&ga, g_A);

    cudaFuncSetAttribute(attn_mma, cudaFuncAttributeMaxDynamicSharedMemorySize,
                         ATTN_SMEM_BYTES);

    dim3 gemm_grid(TT / 128, DD / 128);  // (64, 4)
    dim3 gemm_block(256);

    gemm_mma<<<gemm_grid, gemm_block>>>(q, Wq, bq, gq, TT, DD, DD);
    gemm_mma<<<gemm_grid, gemm_block>>>(q, Wk, bk, gk, TT, DD, DD);
    gemm_mma<<<gemm_grid, gemm_block>>>(q, Wv, bv, gv, TT, DD, DD);

    dim3 attn_grid(SS / QTILE, HH, BB);  // (16, 8, 2)
    attn_mma<<<attn_grid, 256, ATTN_SMEM_BYTES>>>(gq, gk, gv, ga);

    gemm_mma<<<gemm_grid, gemm_block>>>(ga, Wo, bo, out, TT, DD, DD);
}